// round 9
// baseline (speedup 1.0000x reference)
#include <cuda_runtime.h>
#include <cuda_bf16.h>
#include <cstdint>

// q,k,v: [2,12,2048,64] f32; mask: [2,1,1,2048] i32; bias: [1,12,2048,2048] f32
// out region: out [2,12,2048,64] then attn [2,12,2048,2048]
// attn = softmax((q/8)@k^T + bias, masked -> -10000); out = attn @ v
// No-max softmax; QK = 3-term bf16 hi/lo; PV = fp16 with 2^-5 pre-scale.
// WARP-PAIR layout: 512 thr/block; two warps per 16-q-row group.
//   QK: each warp does its 16-key half.  PV: each warp does its 32-d half,
//   with the e tile exchanged through smem (fp16) and re-read as MMA A-frags.
// Halves per-thread registers -> 2 CTAs x 16 warps = 32 warps/SM.

#define TEMPERATURE 8.0f
#define NEG_FILL -10000.0f
#define ESCALE 0.03125f
#define ESCALE_INV 32.0f

constexpr int B_ = 2, H_ = 12, S_ = 2048, D_ = 64;
constexpr int TQ = 128, TK = 32;
constexpr int NKT = S_ / TK;             // 64 tiles
constexpr int NTHR = 512;
// byte offsets from 1024-aligned smem base
constexpr int OFF_QHI  = 0;              // 128 x 128B
constexpr int OFF_QLO  = 16384;
constexpr int OFF_KHI0 = 32768;          // 32 x 128B each
constexpr int OFF_KLO0 = 36864;
constexpr int OFF_VH0  = 40960;
constexpr int OFF_KHI1 = 45056;
constexpr int OFF_KLO1 = 49152;
constexpr int OFF_VH1  = 53248;
constexpr int OFF_RAWK = 57344;          // 32x64 f32 = 8192
constexpr int OFF_RAWV = 65536;
constexpr int OFF_BIAS = 73728;          // 4 chunks x 512 thr x 8B = 16384
constexpr int OFF_E    = 90112;          // 128 rows x 80B = 10240 (fp16 e tile)
constexpr int SMEM_DYN = 100352 + 1024;

// ---------- PTX helpers ----------
__device__ __forceinline__ uint32_t smem_u32(const void* p) {
    return (uint32_t)__cvta_generic_to_shared(p);
}
__device__ __forceinline__ uint32_t pack_bf16(float a, float b) {   // a -> low half
    uint32_t r;
    asm("cvt.rn.bf16x2.f32 %0, %1, %2;" : "=r"(r) : "f"(b), "f"(a));
    return r;
}
__device__ __forceinline__ uint32_t pack_f16(float a, float b) {    // a -> low half
    uint32_t r;
    asm("cvt.rn.f16x2.f32 %0, %1, %2;" : "=r"(r) : "f"(b), "f"(a));
    return r;
}
__device__ __forceinline__ void sts32(uint32_t a, uint32_t x) {
    asm volatile("st.shared.b32 [%0], %1;" :: "r"(a), "r"(x));
}
__device__ __forceinline__ void sts64(uint32_t a, uint32_t x, uint32_t y) {
    asm volatile("st.shared.v2.b32 [%0], {%1,%2};" :: "r"(a), "r"(x), "r"(y));
}
__device__ __forceinline__ float2 lds64f(uint32_t a) {
    float2 r;
    asm volatile("ld.shared.v2.f32 {%0,%1}, [%2];" : "=f"(r.x), "=f"(r.y) : "r"(a));
    return r;
}
__device__ __forceinline__ float4 lds128f(uint32_t a) {
    float4 r;
    asm volatile("ld.shared.v4.f32 {%0,%1,%2,%3}, [%4];"
                 : "=f"(r.x), "=f"(r.y), "=f"(r.z), "=f"(r.w) : "r"(a));
    return r;
}
__device__ __forceinline__ void ldsm_x4(uint32_t addr, uint32_t& r0, uint32_t& r1,
                                        uint32_t& r2, uint32_t& r3) {
    asm volatile("ldmatrix.sync.aligned.m8n8.x4.shared.b16 {%0,%1,%2,%3}, [%4];"
                 : "=r"(r0), "=r"(r1), "=r"(r2), "=r"(r3) : "r"(addr));
}
__device__ __forceinline__ void ldsm_x4t(uint32_t addr, uint32_t& r0, uint32_t& r1,
                                         uint32_t& r2, uint32_t& r3) {
    asm volatile("ldmatrix.sync.aligned.m8n8.x4.trans.shared.b16 {%0,%1,%2,%3}, [%4];"
                 : "=r"(r0), "=r"(r1), "=r"(r2), "=r"(r3) : "r"(addr));
}
__device__ __forceinline__ void mma_bf16(float* c,
                                         uint32_t a0, uint32_t a1, uint32_t a2, uint32_t a3,
                                         uint32_t b0, uint32_t b1) {
    asm volatile(
        "mma.sync.aligned.m16n8k16.row.col.f32.bf16.bf16.f32 "
        "{%0,%1,%2,%3}, {%4,%5,%6,%7}, {%8,%9}, {%0,%1,%2,%3};"
        : "+f"(c[0]), "+f"(c[1]), "+f"(c[2]), "+f"(c[3])
        : "r"(a0), "r"(a1), "r"(a2), "r"(a3), "r"(b0), "r"(b1));
}
__device__ __forceinline__ void mma_f16(float* c,
                                        uint32_t a0, uint32_t a1, uint32_t a2, uint32_t a3,
                                        uint32_t b0, uint32_t b1) {
    asm volatile(
        "mma.sync.aligned.m16n8k16.row.col.f32.f16.f16.f32 "
        "{%0,%1,%2,%3}, {%4,%5,%6,%7}, {%8,%9}, {%0,%1,%2,%3};"
        : "+f"(c[0]), "+f"(c[1]), "+f"(c[2]), "+f"(c[3])
        : "r"(a0), "r"(a1), "r"(a2), "r"(a3), "r"(b0), "r"(b1));
}
__device__ __forceinline__ void split2(float x, float& hi, float& lo) {
    hi = __bfloat162float(__float2bfloat16_rn(x));
    lo = x - hi;
}
__device__ __forceinline__ void cp_async16(uint32_t saddr, const void* gaddr) {
    asm volatile("cp.async.cg.shared.global [%0], [%1], 16;" :: "r"(saddr), "l"(gaddr));
}
__device__ __forceinline__ void cp_async8(uint32_t saddr, const void* gaddr) {
    asm volatile("cp.async.ca.shared.global [%0], [%1], 8;" :: "r"(saddr), "l"(gaddr));
}
__device__ __forceinline__ void cp_commit() {
    asm volatile("cp.async.commit_group;" ::: "memory");
}
__device__ __forceinline__ void cp_wait1() {
    asm volatile("cp.async.wait_group 1;" ::: "memory");
}

// ============== Fused kernel ==============
__global__ __launch_bounds__(NTHR, 2) void attn_k1(
    const float* __restrict__ q, const float* __restrict__ k,
    const float* __restrict__ v, const int* __restrict__ mask,
    const float* __restrict__ bias, float* __restrict__ out,
    float* __restrict__ attn)
{
    extern __shared__ char dynraw[];
    __shared__ float row_half[TQ][2];
    __shared__ float row_inv[TQ];
    char* basep = (char*)(((uintptr_t)dynraw + 1023) & ~(uintptr_t)1023);
    const uint32_t sb = smem_u32(basep);

    const int t    = threadIdx.x;
    const int lane = t & 31;
    const int w    = t >> 5;              // 16 warps
    const int pairp = w >> 1;             // 8 row groups
    const int half  = w & 1;              // 0: keys/d low half, 1: high half
    const int mrow  = pairp * 16;
    const int bh   = blockIdx.y;
    const int b    = bh & 1;
    const int h    = bh >> 1;
    const int q0   = blockIdx.x * TQ;
    const int bhq  = b * H_ + h;

    const float* qb    = q    + ((long)bhq * S_ + q0) * D_;
    const float* kb    = k    + (long)bhq * S_ * D_;
    const float* vb    = v    + (long)bhq * S_ * D_;
    const int*   maskb = mask + (long)b * S_;
    float*       attb  = attn + ((long)bhq * S_ + q0) * S_;
    const float* biasb = bias + ((long)h  * S_ + q0) * S_;

    const int g   = lane >> 2;
    const int qr0 = mrow + g;
    const int qr1 = qr0 + 8;
    const int col_in_tile = half * 16 + (lane & 3) * 2;   // +ntl*8 later

    // ---- prologue prefetch: rawKV(0), bias(0) (thread-exact slots) ----
    cp_async16(sb + OFF_RAWK + t * 16u, kb + t * 4);      // 512 f4 = full 32x64 tile
    cp_async16(sb + OFF_RAWV + t * 16u, vb + t * 4);
    cp_commit();                                          // group rawKV(0)
    #pragma unroll
    for (int j = 0; j < 4; j++) {
        int ntl = j >> 1;
        int row = (j & 1) ? qr1 : qr0;
        cp_async8(sb + OFF_BIAS + j * 4096u + t * 8u,
                  biasb + (long)row * S_ + col_in_tile + ntl * 8);
    }
    cp_commit();                                          // group bias(0)

    // ---- load Q (scaled, hi/lo split), 128B swizzled rows ----
    #pragma unroll
    for (int i = 0; i < 4; i++) {
        int idx4 = t + i * NTHR;           // 2048 f4 = 128x64 f32
        int r  = idx4 >> 4;
        uint32_t cb = (uint32_t)(idx4 & 15) * 8u;
        uint32_t sw = (uint32_t)r * 128u + (cb ^ ((uint32_t)(r & 7) << 4));
        float4 qv = *(const float4*)(qb + idx4 * 4);
        float xh, xl, yh, yl, zh, zl, wh, wl;
        split2(qv.x * (1.0f / TEMPERATURE), xh, xl);
        split2(qv.y * (1.0f / TEMPERATURE), yh, yl);
        split2(qv.z * (1.0f / TEMPERATURE), zh, zl);
        split2(qv.w * (1.0f / TEMPERATURE), wh, wl);
        sts64(sb + OFF_QHI + sw, pack_bf16(xh, yh), pack_bf16(zh, wh));
        sts64(sb + OFF_QLO + sw, pack_bf16(xl, yl), pack_bf16(zl, wl));
    }

    // ---- fragment addresses ----
    const uint32_t xorv = (uint32_t)(lane & 7) << 4;
    const uint32_t qhi_row = sb + OFF_QHI + (uint32_t)(mrow + (lane & 15)) * 128u;
    const uint32_t qlo_row = sb + OFF_QLO + (uint32_t)(mrow + (lane & 15)) * 128u;
    const uint32_t qcol0   = (uint32_t)(lane >> 4) * 16u;
    const uint32_t krow    = (uint32_t)(half * 16 + (lane >> 4) * 8 + (lane & 7)) * 128u;
    const uint32_t kcol0   = (uint32_t)((lane >> 3) & 1) * 16u;
    const uint32_t erow    = sb + OFF_E + (uint32_t)(mrow + (lane & 15)) * 80u
                           + (uint32_t)(lane >> 4) * 16u;
    const uint32_t vrow    = (uint32_t)(lane & 15) * 128u;
    const uint32_t vchunk0 = (uint32_t)(half * 4 + (lane >> 4));

    float accO[4][4];
    #pragma unroll
    for (int i = 0; i < 4; i++)
        #pragma unroll
        for (int j = 0; j < 4; j++) accO[i][j] = 0.0f;
    float sum0 = 0.0f, sum1 = 0.0f;

    for (int kt = 0; kt < NKT; kt++) {
        const int k0 = kt * TK;
        const uint32_t bufb  = (kt & 1) ? (sb + OFF_KHI1) : (sb + OFF_KHI0);
        const uint32_t khi_a = bufb, klo_a = bufb + 4096u, vh_a = bufb + 8192u;

        // 1. wait rawKV(kt) (own chunk), convert into buf[kt&1]
        cp_wait1();
        {
            int r = t >> 4;
            uint32_t cb = (uint32_t)(t & 15) * 8u;
            uint32_t sw = (uint32_t)r * 128u + (cb ^ ((uint32_t)(r & 7) << 4));
            float4 kv = lds128f(sb + OFF_RAWK + t * 16u);
            float xh, xl, yh, yl, zh, zl, wh, wl;
            split2(kv.x, xh, xl); split2(kv.y, yh, yl);
            split2(kv.z, zh, zl); split2(kv.w, wh, wl);
            sts64(khi_a + sw, pack_bf16(xh, yh), pack_bf16(zh, wh));
            sts64(klo_a + sw, pack_bf16(xl, yl), pack_bf16(zl, wl));
            float4 vv = lds128f(sb + OFF_RAWV + t * 16u);
            sts64(vh_a + sw, pack_f16(vv.x, vv.y), pack_f16(vv.z, vv.w));
        }
        // 2. prefetch rawKV(kt+1)
        if (kt + 1 < NKT) {
            cp_async16(sb + OFF_RAWK + t * 16u, kb + (long)(k0 + TK) * D_ + t * 4);
            cp_async16(sb + OFF_RAWV + t * 16u, vb + (long)(k0 + TK) * D_ + t * 4);
        }
        cp_commit();

        // 3. sync A: converts visible
        __syncthreads();

        // 4. QK^T: 16(q) x 16(k) per warp (its key half), 3-term bf16
        float acc[2][4];
        #pragma unroll
        for (int i = 0; i < 2; i++)
            #pragma unroll
            for (int j = 0; j < 4; j++) acc[i][j] = 0.0f;

        #pragma unroll
        for (int ks = 0; ks < 4; ks++) {
            uint32_t ah0, ah1, ah2, ah3, al0, al1, al2, al3;
            uint32_t qoff = (qcol0 + (uint32_t)ks * 32u) ^ xorv;
            ldsm_x4(qhi_row + qoff, ah0, ah1, ah2, ah3);
            ldsm_x4(qlo_row + qoff, al0, al1, al2, al3);
            uint32_t koff = krow + ((kcol0 + (uint32_t)ks * 32u) ^ xorv);
            uint32_t bh0, bh1, bh2, bh3, bl0, bl1, bl2, bl3;
            ldsm_x4(khi_a + koff, bh0, bh1, bh2, bh3);
            ldsm_x4(klo_a + koff, bl0, bl1, bl2, bl3);
            mma_bf16(acc[0], ah0, ah1, ah2, ah3, bh0, bh1);
            mma_bf16(acc[1], ah0, ah1, ah2, ah3, bh2, bh3);
            mma_bf16(acc[0], ah0, ah1, ah2, ah3, bl0, bl1);
            mma_bf16(acc[1], ah0, ah1, ah2, ah3, bl2, bl3);
            mma_bf16(acc[0], al0, al1, al2, al3, bh0, bh1);
            mma_bf16(acc[1], al0, al1, al2, al3, bh2, bh3);
        }

        // 5. wait bias(kt), epilogue: +bias, mask, exp, write e, STS e(fp16)
        cp_wait1();
        #pragma unroll
        for (int ntl = 0; ntl < 2; ntl++) {
            const int ct = col_in_tile + ntl * 8;     // col within tile
            const int gk = k0 + ct;
            const int2 mv = *(const int2*)(maskb + gk);
            float2 bv0 = lds64f(sb + OFF_BIAS + (uint32_t)(ntl * 2 + 0) * 4096u + t * 8u);
            float2 bv1 = lds64f(sb + OFF_BIAS + (uint32_t)(ntl * 2 + 1) * 4096u + t * 8u);
            float l00 = acc[ntl][0] + bv0.x; if (mv.x == 0) l00 = NEG_FILL;
            float l01 = acc[ntl][1] + bv0.y; if (mv.y == 0) l01 = NEG_FILL;
            float l10 = acc[ntl][2] + bv1.x; if (mv.x == 0) l10 = NEG_FILL;
            float l11 = acc[ntl][3] + bv1.y; if (mv.y == 0) l11 = NEG_FILL;
            float e00 = __expf(l00), e01 = __expf(l01);
            float e10 = __expf(l10), e11 = __expf(l11);
            sum0 += e00 + e01;
            sum1 += e10 + e11;
            *(float2*)(attb + (long)qr0 * S_ + gk) = make_float2(e00, e01);
            *(float2*)(attb + (long)qr1 * S_ + gk) = make_float2(e10, e11);
            sts32(sb + OFF_E + (uint32_t)qr0 * 80u + (uint32_t)ct * 2u,
                  pack_f16(e00 * ESCALE, e01 * ESCALE));
            sts32(sb + OFF_E + (uint32_t)qr1 * 80u + (uint32_t)ct * 2u,
                  pack_f16(e10 * ESCALE, e11 * ESCALE));
        }
        // 6. prefetch bias(kt+1)
        if (kt + 1 < NKT) {
            #pragma unroll
            for (int j = 0; j < 4; j++) {
                int ntl = j >> 1;
                int row = (j & 1) ? qr1 : qr0;
                cp_async8(sb + OFF_BIAS + j * 4096u + t * 8u,
                          biasb + (long)row * S_ + (k0 + TK) + col_in_tile + ntl * 8);
            }
        }
        cp_commit();

        // 7. sync B: e tile visible
        __syncthreads();

        // 8. PV: out[16q x 32d-half] += E[16 x 32] @ V[32 x 32-half], fp16
        #pragma unroll
        for (int ks2 = 0; ks2 < 2; ks2++) {
            uint32_t a0, a1, a2, a3;
            ldsm_x4(erow + (uint32_t)ks2 * 32u, a0, a1, a2, a3);
            #pragma unroll
            for (int dnp = 0; dnp < 4; dnp += 2) {
                uint32_t voff = vrow + (uint32_t)ks2 * 2048u
                              + (((vchunk0 + (uint32_t)dnp) * 16u) ^ xorv);
                uint32_t b0, b1, b2, b3;
                ldsm_x4t(vh_a + voff, b0, b1, b2, b3);
                mma_f16(accO[dnp],     a0, a1, a2, a3, b0, b1);
                mma_f16(accO[dnp + 1], a0, a1, a2, a3, b2, b3);
            }
        }
    }

    // ---- row sums: quad-reduce, then combine the two key-halves via smem ----
    sum0 += __shfl_xor_sync(0xffffffffu, sum0, 1);
    sum0 += __shfl_xor_sync(0xffffffffu, sum0, 2);
    sum1 += __shfl_xor_sync(0xffffffffu, sum1, 1);
    sum1 += __shfl_xor_sync(0xffffffffu, sum1, 2);
    if ((lane & 3) == 0) {
        row_half[qr0][half] = sum0;
        row_half[qr1][half] = sum1;
    }
    __syncthreads();
    if (t < TQ) row_inv[t] = 1.0f / (row_half[t][0] + row_half[t][1]);
    __syncthreads();

    // ---- write out (normalized; ESCALE_INV undoes fp16 pre-scale) ----
    const float inv0 = row_inv[qr0] * ESCALE_INV;
    const float inv1 = row_inv[qr1] * ESCALE_INV;
    #pragma unroll
    for (int dn = 0; dn < 4; dn++) {
        const int dc = half * 32 + dn * 8 + (lane & 3) * 2;
        *(float2*)(out + ((long)bhq * S_ + q0 + qr0) * D_ + dc) =
            make_float2(accO[dn][0] * inv0, accO[dn][1] * inv0);
        *(float2*)(out + ((long)bhq * S_ + q0 + qr1) * D_ + dc) =
            make_float2(accO[dn][2] * inv1, accO[dn][3] * inv1);
    }

    // ---- fused normalize: scale own 128 attn rows in place ----
    float4* ab4 = (float4*)attb;
    #pragma unroll 4
    for (int i4 = t; i4 < TQ * S_ / 4; i4 += NTHR) {
        const float inv = row_inv[i4 >> 9];
        float4 x = ab4[i4];
        x.x *= inv; x.y *= inv; x.z *= inv; x.w *= inv;
        ab4[i4] = x;
    }
}

extern "C" void kernel_launch(void* const* d_in, const int* in_sizes, int n_in,
                              void* d_out, int out_size) {
    const float* q    = (const float*)d_in[0];
    const float* k    = (const float*)d_in[1];
    const float* v    = (const float*)d_in[2];
    const int*   mask = (const int*)  d_in[3];
    const float* bias = (const float*)d_in[4];

    float* out  = (float*)d_out;
    float* attn = (float*)d_out + (long)B_ * H_ * S_ * D_;

    static int configured = 0;
    if (!configured) {
        cudaFuncSetAttribute(attn_k1,
                             cudaFuncAttributeMaxDynamicSharedMemorySize, SMEM_DYN);
        configured = 1;
    }

    dim3 grid(S_ / TQ, B_ * H_);        // (16, 24)
    attn_k1<<<grid, NTHR, SMEM_DYN>>>(q, k, v, mask, bias, out, attn);
}

// round 10
// speedup vs baseline: 1.1041x; 1.1041x over previous
#include <cuda_runtime.h>
#include <cuda_bf16.h>
#include <cstdint>

// q,k,v: [2,12,2048,64] f32; mask: [2,1,1,2048] i32; bias: [1,12,2048,2048] f32
// out region: out [2,12,2048,64] then attn [2,12,2048,2048]
// attn = softmax((q/8)@k^T + bias, masked -> -10000); out = attn @ v
// TWO-PASS per block (flash-style): pass 1 computes row sums only (no stores);
// pass 2 recomputes QK, writes final normalized p ONCE, and does PV with fp16 p.
// Cuts attn DRAM traffic 3x (no e write+readback+rewrite). QK = 3-term bf16.
// tcgen05 unavailable (harness targets compute_103 w/o 'a') -> mma.sync path.

#define TEMPERATURE 8.0f
#define NEG_FILL -10000.0f

constexpr int B_ = 2, H_ = 12, S_ = 2048, D_ = 64;
constexpr int TQ = 128;           // q rows per block
constexpr int TK = 64;            // keys per tile
constexpr int NKT = S_ / TK;      // 32
constexpr int LDT = 72;           // 16-bit row stride (padded)
// 16-bit region: Qhi/Qlo (128x72) + Khi/Klo (64x72) + Vh (64x72)
constexpr int BF16_BYTES = (2 * TQ * LDT + 3 * TK * LDT) * 2;   // 64512
constexpr int RAW_BYTES  = 2 * TK * D_ * 4;                     // 32768
constexpr int SMEM_BYTES = BF16_BYTES + RAW_BYTES;              // 97280 -> 2 blocks/SM

// ---------- PTX helpers ----------
__device__ __forceinline__ uint32_t smem_u32(const void* p) {
    return (uint32_t)__cvta_generic_to_shared(p);
}
__device__ __forceinline__ uint32_t pack_bf16(float a, float b) {   // a -> low half
    uint32_t r;
    asm("cvt.rn.bf16x2.f32 %0, %1, %2;" : "=r"(r) : "f"(b), "f"(a));
    return r;
}
__device__ __forceinline__ uint32_t pack_f16(float a, float b) {    // a -> low half
    uint32_t r;
    asm("cvt.rn.f16x2.f32 %0, %1, %2;" : "=r"(r) : "f"(b), "f"(a));
    return r;
}
__device__ __forceinline__ void ldsm_x4(uint32_t addr, uint32_t& r0, uint32_t& r1,
                                        uint32_t& r2, uint32_t& r3) {
    asm volatile("ldmatrix.sync.aligned.m8n8.x4.shared.b16 {%0,%1,%2,%3}, [%4];"
                 : "=r"(r0), "=r"(r1), "=r"(r2), "=r"(r3) : "r"(addr));
}
__device__ __forceinline__ void ldsm_x4t(uint32_t addr, uint32_t& r0, uint32_t& r1,
                                         uint32_t& r2, uint32_t& r3) {
    asm volatile("ldmatrix.sync.aligned.m8n8.x4.trans.shared.b16 {%0,%1,%2,%3}, [%4];"
                 : "=r"(r0), "=r"(r1), "=r"(r2), "=r"(r3) : "r"(addr));
}
__device__ __forceinline__ void mma_bf16(float* c,
                                         uint32_t a0, uint32_t a1, uint32_t a2, uint32_t a3,
                                         uint32_t b0, uint32_t b1) {
    asm volatile(
        "mma.sync.aligned.m16n8k16.row.col.f32.bf16.bf16.f32 "
        "{%0,%1,%2,%3}, {%4,%5,%6,%7}, {%8,%9}, {%0,%1,%2,%3};"
        : "+f"(c[0]), "+f"(c[1]), "+f"(c[2]), "+f"(c[3])
        : "r"(a0), "r"(a1), "r"(a2), "r"(a3), "r"(b0), "r"(b1));
}
__device__ __forceinline__ void mma_f16(float* c,
                                        uint32_t a0, uint32_t a1, uint32_t a2, uint32_t a3,
                                        uint32_t b0, uint32_t b1) {
    asm volatile(
        "mma.sync.aligned.m16n8k16.row.col.f32.f16.f16.f32 "
        "{%0,%1,%2,%3}, {%4,%5,%6,%7}, {%8,%9}, {%0,%1,%2,%3};"
        : "+f"(c[0]), "+f"(c[1]), "+f"(c[2]), "+f"(c[3])
        : "r"(a0), "r"(a1), "r"(a2), "r"(a3), "r"(b0), "r"(b1));
}
__device__ __forceinline__ void split2(float x, float& hi, float& lo) {
    hi = __bfloat162float(__float2bfloat16_rn(x));
    lo = x - hi;
}
__device__ __forceinline__ void cp_async16(uint32_t saddr, const void* gaddr) {
    asm volatile("cp.async.cg.shared.global [%0], [%1], 16;" :: "r"(saddr), "l"(gaddr));
}
__device__ __forceinline__ void cp_commit() {
    asm volatile("cp.async.commit_group;" ::: "memory");
}
__device__ __forceinline__ void cp_wait_all() {
    asm volatile("cp.async.wait_group 0;" ::: "memory");
}

// ============== Fused two-pass kernel ==============
__global__ __launch_bounds__(256, 2) void attn_k1(
    const float* __restrict__ q, const float* __restrict__ k,
    const float* __restrict__ v, const int* __restrict__ mask,
    const float* __restrict__ bias, float* __restrict__ out,
    float* __restrict__ attn)
{
    extern __shared__ char smraw[];
    __nv_bfloat16* sm = (__nv_bfloat16*)smraw;

    __nv_bfloat16* Qhi = sm;
    __nv_bfloat16* Qlo = Qhi + TQ * LDT;
    __nv_bfloat16* Khi = Qlo + TQ * LDT;
    __nv_bfloat16* Klo = Khi + TK * LDT;
    __nv_bfloat16* Vh  = Klo + TK * LDT;                 // fp16 storage
    float* rawK = (float*)(smraw + BF16_BYTES);          // [64*64] f32
    float* rawV = rawK + TK * D_;

    const int t    = threadIdx.x;
    const int lane = t & 31;
    const int w    = t >> 5;            // 8 warps; warp owns q rows 16w..16w+15
    const int bh   = blockIdx.y;
    const int b    = bh & 1;            // b innermost -> bias shared in L2
    const int h    = bh >> 1;
    const int q0   = blockIdx.x * TQ;
    const int bhq  = b * H_ + h;

    const float* qb    = q    + ((long)bhq * S_ + q0) * D_;
    const float* kb    = k    + (long)bhq * S_ * D_;
    const float* vb    = v    + (long)bhq * S_ * D_;
    const int*   maskb = mask + (long)b * S_;
    float*       attb  = attn + ((long)bhq * S_ + q0) * S_;
    const float* biasb = bias + ((long)h  * S_ + q0) * S_;

    const uint32_t rawK_a = smem_u32(rawK);
    const uint32_t rawV_a = smem_u32(rawV);

    // ---- prologue: stage tile 0 K (pass 1 needs no V) ----
    #pragma unroll
    for (int i = 0; i < 4; i++) {
        int idx4 = t + i * 256;          // 1024 f4 = 64x64 f32
        cp_async16(rawK_a + idx4 * 16u, kb + idx4 * 4);
    }
    cp_commit();

    // ---- load Q (scaled, hi/lo split) ----
    #pragma unroll
    for (int i = 0; i < 8; i++) {
        int idx4 = t + i * 256;
        int r  = idx4 >> 4;
        int d4 = (idx4 & 15) * 4;
        float4 qv = *(const float4*)(qb + (long)r * D_ + d4);
        float xh, xl, yh, yl, zh, zl, wh, wl;
        split2(qv.x * (1.0f / TEMPERATURE), xh, xl);
        split2(qv.y * (1.0f / TEMPERATURE), yh, yl);
        split2(qv.z * (1.0f / TEMPERATURE), zh, zl);
        split2(qv.w * (1.0f / TEMPERATURE), wh, wl);
        uint32_t* ph = (uint32_t*)(Qhi + r * LDT + d4);
        uint32_t* pl = (uint32_t*)(Qlo + r * LDT + d4);
        ph[0] = pack_bf16(xh, yh); ph[1] = pack_bf16(zh, wh);
        pl[0] = pack_bf16(xl, yl); pl[1] = pack_bf16(zl, wl);
    }

    const int mrow = w * 16;
    const int g    = lane >> 2;
    const int qr0  = mrow + g;
    const int qr1  = qr0 + 8;

    const uint32_t qa_off = ((uint32_t)(mrow + (lane & 15)) * LDT + 8u * (lane >> 4)) * 2u;
    const uint32_t qhi_base = smem_u32(Qhi) + qa_off;
    const uint32_t qlo_base = smem_u32(Qlo) + qa_off;
    const int kgrp = lane >> 3;
    const uint32_t kx4_off =
        ((uint32_t)((kgrp >> 1) * 8 + (lane & 7)) * LDT + (uint32_t)(kgrp & 1) * 8u) * 2u;
    const uint32_t khi_b = smem_u32(Khi) + kx4_off;
    const uint32_t klo_b = smem_u32(Klo) + kx4_off;
    const uint32_t vx4_off =
        ((uint32_t)(lane & 15) * LDT + (uint32_t)(lane >> 4) * 8u) * 2u;
    const uint32_t vh_b = smem_u32(Vh) + vx4_off;

    float sum0 = 0.0f, sum1 = 0.0f;

    // ================= PASS 1: row sums only (no stores, no V) =================
    for (int kt = 0; kt < NKT; kt++) {
        const int k0 = kt * TK;
        cp_wait_all();
        __syncthreads();

        // convert rawK -> Khi/Klo
        #pragma unroll
        for (int i = 0; i < 4; i++) {
            int idx4 = t + i * 256;
            int r  = idx4 >> 4;
            int d4 = (idx4 & 15) * 4;
            float4 kv = *(const float4*)(rawK + idx4 * 4);
            float xh, xl, yh, yl, zh, zl, wh, wl;
            split2(kv.x, xh, xl); split2(kv.y, yh, yl);
            split2(kv.z, zh, zl); split2(kv.w, wh, wl);
            uint32_t* ph = (uint32_t*)(Khi + r * LDT + d4);
            uint32_t* pl = (uint32_t*)(Klo + r * LDT + d4);
            ph[0] = pack_bf16(xh, yh); ph[1] = pack_bf16(zh, wh);
            pl[0] = pack_bf16(xl, yl); pl[1] = pack_bf16(zl, wl);
        }
        __syncthreads();

        if (kt + 1 < NKT) {
            const float* kn = kb + (long)(k0 + TK) * D_;
            #pragma unroll
            for (int i = 0; i < 4; i++) {
                int idx4 = t + i * 256;
                cp_async16(rawK_a + idx4 * 16u, kn + idx4 * 4);
            }
        }
        cp_commit();

        // QK^T 3-term bf16
        float acc[8][4];
        #pragma unroll
        for (int i = 0; i < 8; i++)
            #pragma unroll
            for (int j = 0; j < 4; j++) acc[i][j] = 0.0f;

        #pragma unroll
        for (int ks = 0; ks < 4; ks++) {
            uint32_t ah0, ah1, ah2, ah3, al0, al1, al2, al3;
            ldsm_x4(qhi_base + ks * 32u, ah0, ah1, ah2, ah3);
            ldsm_x4(qlo_base + ks * 32u, al0, al1, al2, al3);
            #pragma unroll
            for (int ntp = 0; ntp < 8; ntp += 2) {
                const uint32_t off = (uint32_t)(ntp * 8 * LDT) * 2u + ks * 32u;
                uint32_t bh0, bh1, bh2, bh3, bl0, bl1, bl2, bl3;
                ldsm_x4(khi_b + off, bh0, bh1, bh2, bh3);
                ldsm_x4(klo_b + off, bl0, bl1, bl2, bl3);
                mma_bf16(acc[ntp],     ah0, ah1, ah2, ah3, bh0, bh1);
                mma_bf16(acc[ntp],     ah0, ah1, ah2, ah3, bl0, bl1);
                mma_bf16(acc[ntp],     al0, al1, al2, al3, bh0, bh1);
                mma_bf16(acc[ntp + 1], ah0, ah1, ah2, ah3, bh2, bh3);
                mma_bf16(acc[ntp + 1], ah0, ah1, ah2, ah3, bl2, bl3);
                mma_bf16(acc[ntp + 1], al0, al1, al2, al3, bh2, bh3);
            }
        }

        // epilogue: bias, mask, exp, accumulate row sums (NO stores)
        #pragma unroll
        for (int nt = 0; nt < 8; nt++) {
            const int gk = k0 + nt * 8 + (lane & 3) * 2;
            const int2 mv = *(const int2*)(maskb + gk);
            float2 bv0 = *(const float2*)(biasb + (long)qr0 * S_ + gk);
            float2 bv1 = *(const float2*)(biasb + (long)qr1 * S_ + gk);
            float l00 = acc[nt][0] + bv0.x; if (mv.x == 0) l00 = NEG_FILL;
            float l01 = acc[nt][1] + bv0.y; if (mv.y == 0) l01 = NEG_FILL;
            float l10 = acc[nt][2] + bv1.x; if (mv.x == 0) l10 = NEG_FILL;
            float l11 = acc[nt][3] + bv1.y; if (mv.y == 0) l11 = NEG_FILL;
            sum0 += __expf(l00) + __expf(l01);
            sum1 += __expf(l10) + __expf(l11);
        }
    }

    // ---- row inverses: quad-reduce, stay in registers ----
    sum0 += __shfl_xor_sync(0xffffffffu, sum0, 1);
    sum0 += __shfl_xor_sync(0xffffffffu, sum0, 2);
    sum1 += __shfl_xor_sync(0xffffffffu, sum1, 1);
    sum1 += __shfl_xor_sync(0xffffffffu, sum1, 2);
    const float inv0 = 1.0f / sum0;
    const float inv1 = 1.0f / sum1;

    // ---- stage tile 0 K+V for pass 2 ----
    #pragma unroll
    for (int i = 0; i < 4; i++) {
        int idx4 = t + i * 256;
        cp_async16(rawK_a + idx4 * 16u, kb + idx4 * 4);
        cp_async16(rawV_a + idx4 * 16u, vb + idx4 * 4);
    }
    cp_commit();

    float accO[8][4];
    #pragma unroll
    for (int i = 0; i < 8; i++)
        #pragma unroll
        for (int j = 0; j < 4; j++) accO[i][j] = 0.0f;

    // ================= PASS 2: recompute QK, write p once, PV =================
    for (int kt = 0; kt < NKT; kt++) {
        const int k0 = kt * TK;
        cp_wait_all();
        __syncthreads();

        #pragma unroll
        for (int i = 0; i < 4; i++) {
            int idx4 = t + i * 256;
            int r  = idx4 >> 4;
            int d4 = (idx4 & 15) * 4;
            float4 kv = *(const float4*)(rawK + idx4 * 4);
            float xh, xl, yh, yl, zh, zl, wh, wl;
            split2(kv.x, xh, xl); split2(kv.y, yh, yl);
            split2(kv.z, zh, zl); split2(kv.w, wh, wl);
            uint32_t* ph = (uint32_t*)(Khi + r * LDT + d4);
            uint32_t* pl = (uint32_t*)(Klo + r * LDT + d4);
            ph[0] = pack_bf16(xh, yh); ph[1] = pack_bf16(zh, wh);
            pl[0] = pack_bf16(xl, yl); pl[1] = pack_bf16(zl, wl);
            float4 vv = *(const float4*)(rawV + idx4 * 4);
            uint32_t* pv = (uint32_t*)(Vh + r * LDT + d4);
            pv[0] = pack_f16(vv.x, vv.y); pv[1] = pack_f16(vv.z, vv.w);
        }
        __syncthreads();

        if (kt + 1 < NKT) {
            const float* kn = kb + (long)(k0 + TK) * D_;
            const float* vn = vb + (long)(k0 + TK) * D_;
            #pragma unroll
            for (int i = 0; i < 4; i++) {
                int idx4 = t + i * 256;
                cp_async16(rawK_a + idx4 * 16u, kn + idx4 * 4);
                cp_async16(rawV_a + idx4 * 16u, vn + idx4 * 4);
            }
        }
        cp_commit();

        // QK^T 3-term bf16 (identical recompute)
        float acc[8][4];
        #pragma unroll
        for (int i = 0; i < 8; i++)
            #pragma unroll
            for (int j = 0; j < 4; j++) acc[i][j] = 0.0f;

        #pragma unroll
        for (int ks = 0; ks < 4; ks++) {
            uint32_t ah0, ah1, ah2, ah3, al0, al1, al2, al3;
            ldsm_x4(qhi_base + ks * 32u, ah0, ah1, ah2, ah3);
            ldsm_x4(qlo_base + ks * 32u, al0, al1, al2, al3);
            #pragma unroll
            for (int ntp = 0; ntp < 8; ntp += 2) {
                const uint32_t off = (uint32_t)(ntp * 8 * LDT) * 2u + ks * 32u;
                uint32_t bh0, bh1, bh2, bh3, bl0, bl1, bl2, bl3;
                ldsm_x4(khi_b + off, bh0, bh1, bh2, bh3);
                ldsm_x4(klo_b + off, bl0, bl1, bl2, bl3);
                mma_bf16(acc[ntp],     ah0, ah1, ah2, ah3, bh0, bh1);
                mma_bf16(acc[ntp],     ah0, ah1, ah2, ah3, bl0, bl1);
                mma_bf16(acc[ntp],     al0, al1, al2, al3, bh0, bh1);
                mma_bf16(acc[ntp + 1], ah0, ah1, ah2, ah3, bh2, bh3);
                mma_bf16(acc[ntp + 1], ah0, ah1, ah2, ah3, bl2, bl3);
                mma_bf16(acc[ntp + 1], al0, al1, al2, al3, bh2, bh3);
            }
        }

        // epilogue: p = exp(l)*inv, store final attn, build fp16 p frags
        uint32_t pfr[8][2];
        #pragma unroll
        for (int nt = 0; nt < 8; nt++) {
            const int gk = k0 + nt * 8 + (lane & 3) * 2;
            const int2 mv = *(const int2*)(maskb + gk);
            float2 bv0 = *(const float2*)(biasb + (long)qr0 * S_ + gk);
            float2 bv1 = *(const float2*)(biasb + (long)qr1 * S_ + gk);
            float l00 = acc[nt][0] + bv0.x; if (mv.x == 0) l00 = NEG_FILL;
            float l01 = acc[nt][1] + bv0.y; if (mv.y == 0) l01 = NEG_FILL;
            float l10 = acc[nt][2] + bv1.x; if (mv.x == 0) l10 = NEG_FILL;
            float l11 = acc[nt][3] + bv1.y; if (mv.y == 0) l11 = NEG_FILL;
            float p00 = __expf(l00) * inv0, p01 = __expf(l01) * inv0;
            float p10 = __expf(l10) * inv1, p11 = __expf(l11) * inv1;
            *(float2*)(attb + (long)qr0 * S_ + gk) = make_float2(p00, p01);
            *(float2*)(attb + (long)qr1 * S_ + gk) = make_float2(p10, p11);
            pfr[nt][0] = pack_f16(p00, p01);   // row g
            pfr[nt][1] = pack_f16(p10, p11);   // row g+8
        }

        // PV: out[16 x 64] += P[16 x 64] @ V[64 x 64], fp16
        #pragma unroll
        for (int ks2 = 0; ks2 < 4; ks2++) {
            uint32_t a0 = pfr[2 * ks2][0],     a1 = pfr[2 * ks2][1];
            uint32_t a2 = pfr[2 * ks2 + 1][0], a3 = pfr[2 * ks2 + 1][1];
            const uint32_t roff = (uint32_t)(ks2 * 16 * LDT) * 2u;
            #pragma unroll
            for (int dnp = 0; dnp < 8; dnp += 2) {
                uint32_t b0, b1, b2, b3;
                ldsm_x4t(vh_b + roff + dnp * 16u, b0, b1, b2, b3);
                mma_f16(accO[dnp],     a0, a1, a2, a3, b0, b1);
                mma_f16(accO[dnp + 1], a0, a1, a2, a3, b2, b3);
            }
        }
    }

    // ---- write out (p already normalized -> no scaling) ----
    #pragma unroll
    for (int dn = 0; dn < 8; dn++) {
        const int dc = dn * 8 + (lane & 3) * 2;
        *(float2*)(out + ((long)bhq * S_ + q0 + qr0) * D_ + dc) =
            make_float2(accO[dn][0], accO[dn][1]);
        *(float2*)(out + ((long)bhq * S_ + q0 + qr1) * D_ + dc) =
            make_float2(accO[dn][2], accO[dn][3]);
    }
}

extern "C" void kernel_launch(void* const* d_in, const int* in_sizes, int n_in,
                              void* d_out, int out_size) {
    const float* q    = (const float*)d_in[0];
    const float* k    = (const float*)d_in[1];
    const float* v    = (const float*)d_in[2];
    const int*   mask = (const int*)  d_in[3];
    const float* bias = (const float*)d_in[4];

    float* out  = (float*)d_out;
    float* attn = (float*)d_out + (long)B_ * H_ * S_ * D_;

    static int configured = 0;
    if (!configured) {
        cudaFuncSetAttribute(attn_k1,
                             cudaFuncAttributeMaxDynamicSharedMemorySize, SMEM_BYTES);
        configured = 1;
    }

    dim3 grid(S_ / TQ, B_ * H_);        // (16, 24)
    attn_k1<<<grid, 256, SMEM_BYTES>>>(q, k, v, mask, bias, out, attn);
}

// round 11
// speedup vs baseline: 1.2460x; 1.1285x over previous
#include <cuda_runtime.h>
#include <cuda_bf16.h>
#include <cstdint>

// q,k,v: [2,12,2048,64] f32; mask: [2,1,1,2048] i32; bias: [1,12,2048,2048] f32
// out region: out [2,12,2048,64] then attn [2,12,2048,2048]
// attn = softmax((q/8)@k^T + bias, masked -> -10000); out = attn @ v
// Base = R7 winner (431us): single pass, e written once, normalize fused,
// cp.async K/V staging, fp16 PV with 2^-5 pre-scale, QK 3-term bf16.
// R11 delta: term-major MMA ordering (same-acc reuse gap 1 -> 4) and
// non-volatile MMA asm so ptxas can hide HMMA latency. No work change.

#define TEMPERATURE 8.0f
#define NEG_FILL -10000.0f
#define ESCALE 0.03125f
#define ESCALE_INV 32.0f

constexpr int B_ = 2, H_ = 12, S_ = 2048, D_ = 64;
constexpr int TQ = 128, TK = 64;
constexpr int NKT = S_ / TK;      // 32
constexpr int LDT = 72;           // 16-bit row stride (padded)
constexpr int BF16_BYTES = (2 * TQ * LDT + 3 * TK * LDT) * 2;   // Qhi/Qlo/Khi/Klo/Vh
constexpr int RAW_BYTES  = 2 * TK * D_ * 4;
constexpr int SMEM_BYTES = BF16_BYTES + RAW_BYTES;              // 97280 -> 2 blocks/SM

// ---------- PTX helpers ----------
__device__ __forceinline__ uint32_t smem_u32(const void* p) {
    return (uint32_t)__cvta_generic_to_shared(p);
}
__device__ __forceinline__ uint32_t pack_bf16(float a, float b) {   // a -> low half
    uint32_t r;
    asm("cvt.rn.bf16x2.f32 %0, %1, %2;" : "=r"(r) : "f"(b), "f"(a));
    return r;
}
__device__ __forceinline__ uint32_t pack_f16(float a, float b) {
    uint32_t r;
    asm("cvt.rn.f16x2.f32 %0, %1, %2;" : "=r"(r) : "f"(b), "f"(a));
    return r;
}
__device__ __forceinline__ void ldsm_x4(uint32_t addr, uint32_t& r0, uint32_t& r1,
                                        uint32_t& r2, uint32_t& r3) {
    asm volatile("ldmatrix.sync.aligned.m8n8.x4.shared.b16 {%0,%1,%2,%3}, [%4];"
                 : "=r"(r0), "=r"(r1), "=r"(r2), "=r"(r3) : "r"(addr));
}
__device__ __forceinline__ void ldsm_x4t(uint32_t addr, uint32_t& r0, uint32_t& r1,
                                         uint32_t& r2, uint32_t& r3) {
    asm volatile("ldmatrix.sync.aligned.m8n8.x4.trans.shared.b16 {%0,%1,%2,%3}, [%4];"
                 : "=r"(r0), "=r"(r1), "=r"(r2), "=r"(r3) : "r"(addr));
}
// NOTE: NOT volatile -> ptxas may reschedule to hide HMMA latency.
__device__ __forceinline__ void mma_bf16(float* c,
                                         uint32_t a0, uint32_t a1, uint32_t a2, uint32_t a3,
                                         uint32_t b0, uint32_t b1) {
    asm("mma.sync.aligned.m16n8k16.row.col.f32.bf16.bf16.f32 "
        "{%0,%1,%2,%3}, {%4,%5,%6,%7}, {%8,%9}, {%0,%1,%2,%3};"
        : "+f"(c[0]), "+f"(c[1]), "+f"(c[2]), "+f"(c[3])
        : "r"(a0), "r"(a1), "r"(a2), "r"(a3), "r"(b0), "r"(b1));
}
__device__ __forceinline__ void mma_f16(float* c,
                                        uint32_t a0, uint32_t a1, uint32_t a2, uint32_t a3,
                                        uint32_t b0, uint32_t b1) {
    asm("mma.sync.aligned.m16n8k16.row.col.f32.f16.f16.f32 "
        "{%0,%1,%2,%3}, {%4,%5,%6,%7}, {%8,%9}, {%0,%1,%2,%3};"
        : "+f"(c[0]), "+f"(c[1]), "+f"(c[2]), "+f"(c[3])
        : "r"(a0), "r"(a1), "r"(a2), "r"(a3), "r"(b0), "r"(b1));
}
__device__ __forceinline__ void split2(float x, float& hi, float& lo) {
    hi = __bfloat162float(__float2bfloat16_rn(x));
    lo = x - hi;
}
__device__ __forceinline__ void cp_async16(uint32_t saddr, const void* gaddr) {
    asm volatile("cp.async.cg.shared.global [%0], [%1], 16;" :: "r"(saddr), "l"(gaddr));
}
__device__ __forceinline__ void cp_commit() {
    asm volatile("cp.async.commit_group;" ::: "memory");
}
__device__ __forceinline__ void cp_wait_all() {
    asm volatile("cp.async.wait_group 0;" ::: "memory");
}

// ============== Fused kernel: e=exp(logits), rowsums, out, attn normalize =======
__global__ __launch_bounds__(256, 2) void attn_k1(
    const float* __restrict__ q, const float* __restrict__ k,
    const float* __restrict__ v, const int* __restrict__ mask,
    const float* __restrict__ bias, float* __restrict__ out,
    float* __restrict__ attn)
{
    extern __shared__ char smraw[];
    __shared__ float row_inv[TQ];
    __nv_bfloat16* sm = (__nv_bfloat16*)smraw;

    __nv_bfloat16* Qhi = sm;
    __nv_bfloat16* Qlo = Qhi + TQ * LDT;
    __nv_bfloat16* Khi = Qlo + TQ * LDT;
    __nv_bfloat16* Klo = Khi + TK * LDT;
    __nv_bfloat16* Vh  = Klo + TK * LDT;                 // fp16 bits
    float* rawK = (float*)(smraw + BF16_BYTES);
    float* rawV = rawK + TK * D_;

    const int t    = threadIdx.x;
    const int lane = t & 31;
    const int w    = t >> 5;
    const int bh   = blockIdx.y;
    const int b    = bh & 1;
    const int h    = bh >> 1;
    const int q0   = blockIdx.x * TQ;
    const int bhq  = b * H_ + h;

    const float* qb    = q    + ((long)bhq * S_ + q0) * D_;
    const float* kb    = k    + (long)bhq * S_ * D_;
    const float* vb    = v    + (long)bhq * S_ * D_;
    const int*   maskb = mask + (long)b * S_;
    float*       attb  = attn + ((long)bhq * S_ + q0) * S_;
    const float* biasb = bias + ((long)h  * S_ + q0) * S_;

    // ---- prologue: stage tile 0 K/V raw via cp.async ----
    const uint32_t rawK_a = smem_u32(rawK);
    const uint32_t rawV_a = smem_u32(rawV);
    #pragma unroll
    for (int i = 0; i < 4; i++) {
        int idx4 = t + i * 256;
        cp_async16(rawK_a + idx4 * 16u, kb + idx4 * 4);
        cp_async16(rawV_a + idx4 * 16u, vb + idx4 * 4);
    }
    cp_commit();

    // ---- load Q (scaled, hi/lo split) ----
    #pragma unroll
    for (int i = 0; i < 8; i++) {
        int idx4 = t + i * 256;
        int r  = idx4 >> 4;
        int d4 = (idx4 & 15) * 4;
        float4 qv = *(const float4*)(qb + (long)r * D_ + d4);
        float xh, xl, yh, yl, zh, zl, wh, wl;
        split2(qv.x * (1.0f / TEMPERATURE), xh, xl);
        split2(qv.y * (1.0f / TEMPERATURE), yh, yl);
        split2(qv.z * (1.0f / TEMPERATURE), zh, zl);
        split2(qv.w * (1.0f / TEMPERATURE), wh, wl);
        uint32_t* ph = (uint32_t*)(Qhi + r * LDT + d4);
        uint32_t* pl = (uint32_t*)(Qlo + r * LDT + d4);
        ph[0] = pack_bf16(xh, yh); ph[1] = pack_bf16(zh, wh);
        pl[0] = pack_bf16(xl, yl); pl[1] = pack_bf16(zl, wl);
    }

    const int mrow = w * 16;
    const int g    = lane >> 2;
    const int qr0  = mrow + g;
    const int qr1  = qr0 + 8;

    const uint32_t qa_off = ((uint32_t)(mrow + (lane & 15)) * LDT + 8u * (lane >> 4)) * 2u;
    const uint32_t qhi_base = smem_u32(Qhi) + qa_off;
    const uint32_t qlo_base = smem_u32(Qlo) + qa_off;
    const int kgrp = lane >> 3;
    const uint32_t kx4_off =
        ((uint32_t)((kgrp >> 1) * 8 + (lane & 7)) * LDT + (uint32_t)(kgrp & 1) * 8u) * 2u;
    const uint32_t khi_b = smem_u32(Khi) + kx4_off;
    const uint32_t klo_b = smem_u32(Klo) + kx4_off;
    const uint32_t vx4_off =
        ((uint32_t)(lane & 15) * LDT + (uint32_t)(lane >> 4) * 8u) * 2u;
    const uint32_t vh_b = smem_u32(Vh) + vx4_off;

    float accO[8][4];
    #pragma unroll
    for (int i = 0; i < 8; i++)
        #pragma unroll
        for (int j = 0; j < 4; j++) accO[i][j] = 0.0f;
    float sum0 = 0.0f, sum1 = 0.0f;

    for (int kt = 0; kt < NKT; kt++) {
        const int k0 = kt * TK;
        cp_wait_all();
        __syncthreads();

        // ---- convert raw (smem) -> K bf16 hi/lo, V fp16 ----
        #pragma unroll
        for (int i = 0; i < 4; i++) {
            int idx4 = t + i * 256;
            int r  = idx4 >> 4;
            int d4 = (idx4 & 15) * 4;
            float4 kv = *(const float4*)(rawK + idx4 * 4);
            float xh, xl, yh, yl, zh, zl, wh, wl;
            split2(kv.x, xh, xl); split2(kv.y, yh, yl);
            split2(kv.z, zh, zl); split2(kv.w, wh, wl);
            uint32_t* ph = (uint32_t*)(Khi + r * LDT + d4);
            uint32_t* pl = (uint32_t*)(Klo + r * LDT + d4);
            ph[0] = pack_bf16(xh, yh); ph[1] = pack_bf16(zh, wh);
            pl[0] = pack_bf16(xl, yl); pl[1] = pack_bf16(zl, wl);
            float4 vv = *(const float4*)(rawV + idx4 * 4);
            uint32_t* pv = (uint32_t*)(Vh + r * LDT + d4);
            pv[0] = pack_f16(vv.x, vv.y); pv[1] = pack_f16(vv.z, vv.w);
        }
        __syncthreads();

        // ---- stage next tile's raw K/V ----
        if (kt + 1 < NKT) {
            const float* knext = kb + (long)(k0 + TK) * D_;
            const float* vnext = vb + (long)(k0 + TK) * D_;
            #pragma unroll
            for (int i = 0; i < 4; i++) {
                int idx4 = t + i * 256;
                cp_async16(rawK_a + idx4 * 16u, knext + idx4 * 4);
                cp_async16(rawV_a + idx4 * 16u, vnext + idx4 * 4);
            }
            cp_commit();
        }

        // ---- QK^T, 3-term bf16, TERM-MAJOR issue order ----
        float acc[8][4];
        #pragma unroll
        for (int i = 0; i < 8; i++)
            #pragma unroll
            for (int j = 0; j < 4; j++) acc[i][j] = 0.0f;

        #pragma unroll
        for (int ks = 0; ks < 4; ks++) {
            uint32_t ah0, ah1, ah2, ah3, al0, al1, al2, al3;
            ldsm_x4(qhi_base + ks * 32u, ah0, ah1, ah2, ah3);
            ldsm_x4(qlo_base + ks * 32u, al0, al1, al2, al3);
            #pragma unroll
            for (int hg = 0; hg < 2; hg++) {            // 4 n-tiles per group
                const int nt0 = hg * 4;
                const uint32_t o0 = (uint32_t)(nt0 * 8 * LDT) * 2u + ks * 32u;
                const uint32_t o1 = (uint32_t)((nt0 + 2) * 8 * LDT) * 2u + ks * 32u;
                uint32_t kh[8], kl[8];
                ldsm_x4(khi_b + o0, kh[0], kh[1], kh[2], kh[3]);
                ldsm_x4(khi_b + o1, kh[4], kh[5], kh[6], kh[7]);
                ldsm_x4(klo_b + o0, kl[0], kl[1], kl[2], kl[3]);
                ldsm_x4(klo_b + o1, kl[4], kl[5], kl[6], kl[7]);
                // term hh: 4 independent accumulators back-to-back
                mma_bf16(acc[nt0 + 0], ah0, ah1, ah2, ah3, kh[0], kh[1]);
                mma_bf16(acc[nt0 + 1], ah0, ah1, ah2, ah3, kh[2], kh[3]);
                mma_bf16(acc[nt0 + 2], ah0, ah1, ah2, ah3, kh[4], kh[5]);
                mma_bf16(acc[nt0 + 3], ah0, ah1, ah2, ah3, kh[6], kh[7]);
                // term hl
                mma_bf16(acc[nt0 + 0], ah0, ah1, ah2, ah3, kl[0], kl[1]);
                mma_bf16(acc[nt0 + 1], ah0, ah1, ah2, ah3, kl[2], kl[3]);
                mma_bf16(acc[nt0 + 2], ah0, ah1, ah2, ah3, kl[4], kl[5]);
                mma_bf16(acc[nt0 + 3], ah0, ah1, ah2, ah3, kl[6], kl[7]);
                // term lh
                mma_bf16(acc[nt0 + 0], al0, al1, al2, al3, kh[0], kh[1]);
                mma_bf16(acc[nt0 + 1], al0, al1, al2, al3, kh[2], kh[3]);
                mma_bf16(acc[nt0 + 2], al0, al1, al2, al3, kh[4], kh[5]);
                mma_bf16(acc[nt0 + 3], al0, al1, al2, al3, kh[6], kh[7]);
            }
        }

        // ---- epilogue: bias, mask, exp, write e, build fp16 PV A-frags ----
        uint32_t efr[8][2];
        #pragma unroll
        for (int nt = 0; nt < 8; nt++) {
            const int gk = k0 + nt * 8 + (lane & 3) * 2;
            const int2 mv = *(const int2*)(maskb + gk);
            float2 bv0 = *(const float2*)(biasb + (long)qr0 * S_ + gk);
            float2 bv1 = *(const float2*)(biasb + (long)qr1 * S_ + gk);
            float l00 = acc[nt][0] + bv0.x; if (mv.x == 0) l00 = NEG_FILL;
            float l01 = acc[nt][1] + bv0.y; if (mv.y == 0) l01 = NEG_FILL;
            float l10 = acc[nt][2] + bv1.x; if (mv.x == 0) l10 = NEG_FILL;
            float l11 = acc[nt][3] + bv1.y; if (mv.y == 0) l11 = NEG_FILL;
            float e00 = __expf(l00), e01 = __expf(l01);
            float e10 = __expf(l10), e11 = __expf(l11);
            sum0 += e00 + e01;
            sum1 += e10 + e11;
            *(float2*)(attb + (long)qr0 * S_ + gk) = make_float2(e00, e01);
            *(float2*)(attb + (long)qr1 * S_ + gk) = make_float2(e10, e11);
            efr[nt][0] = pack_f16(e00 * ESCALE, e01 * ESCALE);
            efr[nt][1] = pack_f16(e10 * ESCALE, e11 * ESCALE);
        }

        // ---- PV: out[16 x 64] += E[16 x 64] @ V[64 x 64], fp16 ----
        #pragma unroll
        for (int ks2 = 0; ks2 < 4; ks2++) {
            uint32_t a0 = efr[2 * ks2][0],     a1 = efr[2 * ks2][1];
            uint32_t a2 = efr[2 * ks2 + 1][0], a3 = efr[2 * ks2 + 1][1];
            const uint32_t roff = (uint32_t)(ks2 * 16 * LDT) * 2u;
            #pragma unroll
            for (int dnp = 0; dnp < 8; dnp += 2) {
                uint32_t b0, b1, b2, b3;
                ldsm_x4t(vh_b + roff + dnp * 16u, b0, b1, b2, b3);
                mma_f16(accO[dnp],     a0, a1, a2, a3, b0, b1);
                mma_f16(accO[dnp + 1], a0, a1, a2, a3, b2, b3);
            }
        }
    }

    // ---- row sums: quad-reduce ----
    sum0 += __shfl_xor_sync(0xffffffffu, sum0, 1);
    sum0 += __shfl_xor_sync(0xffffffffu, sum0, 2);
    sum1 += __shfl_xor_sync(0xffffffffu, sum1, 1);
    sum1 += __shfl_xor_sync(0xffffffffu, sum1, 2);
    const float inv0 = 1.0f / sum0;
    const float inv1 = 1.0f / sum1;
    if ((lane & 3) == 0) {
        row_inv[qr0] = inv0;
        row_inv[qr1] = inv1;
    }

    // ---- write out (normalized; ESCALE_INV undoes fp16 pre-scale) ----
    #pragma unroll
    for (int dn = 0; dn < 8; dn++) {
        const int dc = dn * 8 + (lane & 3) * 2;
        *(float2*)(out + ((long)bhq * S_ + q0 + qr0) * D_ + dc) =
            make_float2(accO[dn][0] * inv0 * ESCALE_INV, accO[dn][1] * inv0 * ESCALE_INV);
        *(float2*)(out + ((long)bhq * S_ + q0 + qr1) * D_ + dc) =
            make_float2(accO[dn][2] * inv1 * ESCALE_INV, accO[dn][3] * inv1 * ESCALE_INV);
    }

    // ---- fused normalize: scale own 128 attn rows in place ----
    __syncthreads();
    float4* ab4 = (float4*)attb;
    #pragma unroll 4
    for (int i4 = t; i4 < TQ * S_ / 4; i4 += 256) {
        const float inv = row_inv[i4 >> 9];
        float4 x = ab4[i4];
        x.x *= inv; x.y *= inv; x.z *= inv; x.w *= inv;
        ab4[i4] = x;
    }
}

extern "C" void kernel_launch(void* const* d_in, const int* in_sizes, int n_in,
                              void* d_out, int out_size) {
    const float* q    = (const float*)d_in[0];
    const float* k    = (const float*)d_in[1];
    const float* v    = (const float*)d_in[2];
    const int*   mask = (const int*)  d_in[3];
    const float* bias = (const float*)d_in[4];

    float* out  = (float*)d_out;
    float* attn = (float*)d_out + (long)B_ * H_ * S_ * D_;

    static int configured = 0;
    if (!configured) {
        cudaFuncSetAttribute(attn_k1,
                             cudaFuncAttributeMaxDynamicSharedMemorySize, SMEM_BYTES);
        configured = 1;
    }

    dim3 grid(S_ / TQ, B_ * H_);        // (16, 24)
    attn_k1<<<grid, 256, SMEM_BYTES>>>(q, k, v, mask, bias, out, attn);
}